// round 2
// baseline (speedup 1.0000x reference)
#include <cuda_runtime.h>
#include <cuda_bf16.h>

// SegEncodeLoss: per 32x32 block multi-hot class presence, BCE-with-logits vs preds, mean.
// Shapes fixed by the problem: B=32, H=W=1024, G=32, C=19 -> n_blocks = 32768.

#define NUM_C   19
#define GSZ     32
#define BATCH   32
#define HDIM    1024
#define WDIM    1024
#define NBLK    (BATCH * (HDIM / GSZ) * (WDIM / GSZ))   // 32768
#define WARPS_PER_CTA 8

__device__ double g_acc;

__global__ void seg_init_k() { g_acc = 0.0; }

__global__ __launch_bounds__(WARPS_PER_CTA * 32)
void seg_loss_k(const float* __restrict__ preds, const int* __restrict__ targets) {
    __shared__ float s_acc;
    const int tid  = threadIdx.x;
    if (tid == 0) s_acc = 0.0f;
    __syncthreads();

    const int wid  = tid >> 5;
    const int lane = tid & 31;

    // global block index n = b*1024 + hb*32 + wb  (matches reference reshape/transpose)
    const int n  = blockIdx.x * WARPS_PER_CTA + wid;
    const int b  = n >> 10;
    const int hb = (n >> 5) & 31;
    const int wb = n & 31;

    // Warp covers the 32x32 tile. lane -> (subrow = lane/8, 16B column group = lane%8).
    // Each iteration loads 4 rows x 32 cols; every 8-lane group is a contiguous 128B line.
    const int4* base = (const int4*)(targets
                        + ((size_t)b * HDIM + (size_t)hb * GSZ) * WDIM
                        + (size_t)wb * GSZ);
    const int r0 = lane >> 3;
    const int cg = lane & 7;

    unsigned mask = 0u;
    #pragma unroll
    for (int it = 0; it < 8; ++it) {
        const int row = it * 4 + r0;
        int4 v = base[row * (WDIM / 4) + cg];
        mask |= (1u << v.x) | (1u << v.y) | (1u << v.z) | (1u << v.w);
    }
    mask = __reduce_or_sync(0xffffffffu, mask);

    // BCE-with-logits: loss = softplus(x) - t*x  (stable softplus)
    float val = 0.0f;
    if (lane < NUM_C) {
        const float x  = preds[n * NUM_C + lane];
        const float sp = fmaxf(x, 0.0f) + log1pf(__expf(-fabsf(x)));
        val = sp - (((mask >> lane) & 1u) ? x : 0.0f);
    }
    #pragma unroll
    for (int off = 16; off; off >>= 1)
        val += __shfl_down_sync(0xffffffffu, val, off);
    if (lane == 0) atomicAdd(&s_acc, val);

    __syncthreads();
    if (tid == 0) atomicAdd(&g_acc, (double)s_acc);
}

__global__ void seg_fin_k(float* __restrict__ out) {
    out[0] = (float)(g_acc / (double)((long long)NBLK * NUM_C));
}

extern "C" void kernel_launch(void* const* d_in, const int* in_sizes, int n_in,
                              void* d_out, int out_size) {
    const float* preds   = (const float*)d_in[0];
    const int*   targets = (const int*)d_in[1];
    // d_in[2] = grid_size (fixed at 32; shapes hardcoded)

    seg_init_k<<<1, 1>>>();
    seg_loss_k<<<NBLK / WARPS_PER_CTA, WARPS_PER_CTA * 32>>>(preds, targets);
    seg_fin_k<<<1, 1>>>((float*)d_out);
}

// round 3
// speedup vs baseline: 1.1498x; 1.1498x over previous
#include <cuda_runtime.h>
#include <cuda_bf16.h>

// SegEncodeLoss: per 32x32 block multi-hot class presence, BCE-with-logits vs preds, mean.
// Shapes fixed by the problem: B=32, H=W=1024, G=32, C=19 -> n_blocks = 32768.
// Single fused kernel: threadfence-reduction, last CTA finalizes AND resets the
// device accumulators so every graph replay sees identical starting state.

#define NUM_C   19
#define GSZ     32
#define BATCH   32
#define HDIM    1024
#define WDIM    1024
#define NBLK    (BATCH * (HDIM / GSZ) * (WDIM / GSZ))   // 32768
#define WARPS_PER_CTA 8
#define NCTA    (NBLK / WARPS_PER_CTA)                   // 4096

__device__ double       g_acc;    // zero-init at module load; last CTA re-zeros
__device__ unsigned int g_count;  // ditto

__global__ __launch_bounds__(WARPS_PER_CTA * 32)
void seg_loss_k(const float* __restrict__ preds, const int* __restrict__ targets,
                float* __restrict__ out) {
    __shared__ float s_acc;
    const int tid  = threadIdx.x;
    if (tid == 0) s_acc = 0.0f;
    __syncthreads();

    const int wid  = tid >> 5;
    const int lane = tid & 31;

    // global block index n = b*1024 + hb*32 + wb  (matches reference reshape/transpose)
    const int n  = blockIdx.x * WARPS_PER_CTA + wid;
    const int b  = n >> 10;
    const int hb = (n >> 5) & 31;
    const int wb = n & 31;

    // Warp covers the 32x32 tile. lane -> (subrow = lane/8, 16B column group = lane%8).
    // Each iteration loads 4 rows x 32 cols; every 8-lane group is a contiguous 128B line.
    const int4* base = (const int4*)(targets
                        + ((size_t)b * HDIM + (size_t)hb * GSZ) * WDIM
                        + (size_t)wb * GSZ);
    const int r0 = lane >> 3;
    const int cg = lane & 7;

    unsigned mask = 0u;
    #pragma unroll
    for (int it = 0; it < 8; ++it) {
        const int row = it * 4 + r0;
        int4 v = __ldcs(&base[row * (WDIM / 4) + cg]);   // stream: read-once data
        mask |= (1u << v.x) | (1u << v.y) | (1u << v.z) | (1u << v.w);
    }
    mask = __reduce_or_sync(0xffffffffu, mask);

    // BCE-with-logits: loss = softplus(x) - t*x  (stable softplus)
    float val = 0.0f;
    if (lane < NUM_C) {
        const float x  = preds[n * NUM_C + lane];
        const float sp = fmaxf(x, 0.0f) + log1pf(__expf(-fabsf(x)));
        val = sp - (((mask >> lane) & 1u) ? x : 0.0f);
    }
    #pragma unroll
    for (int off = 16; off; off >>= 1)
        val += __shfl_down_sync(0xffffffffu, val, off);
    if (lane == 0) atomicAdd(&s_acc, val);

    __syncthreads();
    if (tid == 0) {
        atomicAdd(&g_acc, (double)s_acc);
        __threadfence();
        unsigned ticket = atomicAdd(&g_count, 1u);
        if (ticket == NCTA - 1) {
            // All other CTAs' g_acc contributions are visible (fence + atomic order).
            out[0] = (float)(g_acc / (double)((long long)NBLK * NUM_C));
            // Restore state for the next graph replay.
            g_acc   = 0.0;
            g_count = 0u;
        }
    }
}

extern "C" void kernel_launch(void* const* d_in, const int* in_sizes, int n_in,
                              void* d_out, int out_size) {
    const float* preds   = (const float*)d_in[0];
    const int*   targets = (const int*)d_in[1];
    // d_in[2] = grid_size (fixed at 32; shapes hardcoded)

    seg_loss_k<<<NCTA, WARPS_PER_CTA * 32>>>(preds, targets, (float*)d_out);
}